// round 6
// baseline (speedup 1.0000x reference)
#include <cuda_runtime.h>

// RNN forward, fused persistent kernel. B=256, T=1024, IN=4, H=256, OUT=1.
// R5 (resubmit after infra failure): 128 CTAs x 512 threads (16 warps, occ 25%).
// CTA = 2 batches. Split: kg = w&3 (64 k each), hg = w>>2 (64 h each),
// 2 h-rows/thread. Wh: 48 u64-pairs/thread in regs + 8 ulonglong2/step from smem.
// Tail: every thread reduces exactly one (batch, h): 4 LDS + 1 tanh.

typedef unsigned long long u64;

#define T_LEN   1024

__device__ __forceinline__ u64 ffma2(u64 a, u64 b, u64 c) {
    u64 d;
    asm("fma.rn.f32x2 %0, %1, %2, %3;" : "=l"(d) : "l"(a), "l"(b), "l"(c));
    return d;
}
__device__ __forceinline__ float lo32(u64 v) { return __uint_as_float((unsigned)(v & 0xffffffffu)); }
__device__ __forceinline__ float hi32(u64 v) { return __uint_as_float((unsigned)(v >> 32)); }

// shared memory byte offsets
#define SM_WHS   0                  // ulonglong2 WHS[16][8][32]   = 65536 B
#define SM_PART  65536              // float part[8][256]          = 8192 B
#define SM_HBUF  73728              // float hbuf[2][2][256]       = 4096 B
#define SM_XS    77824              // float xs[2][2][4]           = 64 B
#define SM_TOTAL 77888

__global__ void __launch_bounds__(512, 1)
rnn_kernel(const float* __restrict__ x,        // [256][1024][4]
           const float* __restrict__ W_i2h,    // [256][260]  (cols 0..3 = Wx, 4..259 = Wh)
           const float* __restrict__ b_i2h,    // [256]
           const float* __restrict__ W_h2o,    // [256]
           const float* __restrict__ b_h2o,    // [1]
           const float* __restrict__ init_h,   // [256]
           float* __restrict__ out)            // [256]
{
    extern __shared__ unsigned char sm[];
    ulonglong2* WHS = (ulonglong2*)(sm + SM_WHS);
    float* part = (float*)(sm + SM_PART);       // part[kg*2+b][h]
    float* hbuf = (float*)(sm + SM_HBUF);       // hbuf[buf][b][256]
    float* xs   = (float*)(sm + SM_XS);         // xs[buf][b][4]

    const int t  = threadIdx.x;                 // 0..511
    const int w  = t >> 5;                      // 0..15
    const int l  = t & 31;
    const int kg = w & 3;                       // k in [64*kg, 64*kg+64)
    const int hg = w >> 2;                      // h in [64*hg, 64*hg+64)
    const int kbase = kg * 64;

    const int b0 = blockIdx.x * 2;
    const int rA = hg * 64 + l;                 // this thread's 2 h-rows
    const int rB = rA + 32;

    // ---- Wh: rowA all 32 pairs + rowB pairs 0..15 in regs (48 pairs = 96 regs);
    //      rowB pairs 16..31 in smem (8 ulonglong2 per thread = 64KB/CTA) ----
    u64 wreg[48];
    {
        const ulonglong2* rpA = (const ulonglong2*)(W_i2h + (size_t)rA * 260 + 4 + kbase);
        #pragma unroll
        for (int jj = 0; jj < 16; jj++) {
            ulonglong2 v = rpA[jj];
            wreg[2*jj]     = v.x;
            wreg[2*jj + 1] = v.y;
        }
        const ulonglong2* rpB = (const ulonglong2*)(W_i2h + (size_t)rB * 260 + 4 + kbase);
        #pragma unroll
        for (int jj = 0; jj < 8; jj++) {
            ulonglong2 v = rpB[jj];
            wreg[32 + 2*jj]     = v.x;
            wreg[32 + 2*jj + 1] = v.y;
        }
        #pragma unroll
        for (int jj = 8; jj < 16; jj++)
            WHS[(w*8 + (jj - 8))*32 + l] = rpB[jj];
    }

    // reducer role: one (batch, h) per thread
    const int rb = t >> 8;                      // 0 or 1
    const int rh = t & 255;                     // h index
    const float4 wx = *(const float4*)(W_i2h + (size_t)rh * 260);   // Wx[rh][0..3]
    const float bi = b_i2h[rh];

    // init hidden state (buffer 0) and x for step 0
    if (t < 256) {
        float hv = init_h[t];
        hbuf[0*512 + 0*256 + t] = hv;
        hbuf[0*512 + 1*256 + t] = hv;
    }
    if (t < 2) {
        float4 xv = *(const float4*)(x + ((size_t)(b0 + t) * T_LEN + 0) * 4);
        *(float4*)(xs + t*4) = xv;
    }
    __syncthreads();

    float pool = 0.0f;
    int cur = 0;

    for (int step = 0; step < T_LEN; step++) {
        const int nxt = cur ^ 1;

        // ---- FMA phase: partial dot products over this warp's 64-k slice ----
        const ulonglong2* hp0 = (const ulonglong2*)(hbuf + cur*512 + 0*256 + kbase);
        const ulonglong2* hp1 = (const ulonglong2*)(hbuf + cur*512 + 1*256 + kbase);

        u64 aA0 = 0ULL, aA1 = 0ULL, aB0 = 0ULL, aB1 = 0ULL;

        #pragma unroll
        for (int jj = 0; jj < 16; jj++) {
            ulonglong2 h0v = hp0[jj];
            ulonglong2 h1v = hp1[jj];
            u64 wa = wreg[2*jj];
            u64 wb = wreg[2*jj + 1];
            aA0 = ffma2(wa, h0v.x, aA0);
            aA0 = ffma2(wb, h0v.y, aA0);
            aA1 = ffma2(wa, h1v.x, aA1);
            aA1 = ffma2(wb, h1v.y, aA1);
            u64 wa2, wb2;
            if (jj < 8) { wa2 = wreg[32 + 2*jj]; wb2 = wreg[32 + 2*jj + 1]; }
            else { ulonglong2 v = WHS[(w*8 + (jj - 8))*32 + l]; wa2 = v.x; wb2 = v.y; }
            aB0 = ffma2(wa2, h0v.x, aB0);
            aB0 = ffma2(wb2, h0v.y, aB0);
            aB1 = ffma2(wa2, h1v.x, aB1);
            aB1 = ffma2(wb2, h1v.y, aB1);
        }

        // partial sums: part[kg*2+b][h]
        part[(kg*2 + 0)*256 + rA] = lo32(aA0) + hi32(aA0);
        part[(kg*2 + 1)*256 + rA] = lo32(aA1) + hi32(aA1);
        part[(kg*2 + 0)*256 + rB] = lo32(aB0) + hi32(aB0);
        part[(kg*2 + 1)*256 + rB] = lo32(aB1) + hi32(aB1);

        // stage x for next step
        if (t < 2) {
            int tn = (step < T_LEN - 1) ? (step + 1) : step;
            float4 xv = *(const float4*)(x + ((size_t)(b0 + t) * T_LEN + tn) * 4);
            *(float4*)(xs + nxt*8 + t*4) = xv;
        }
        __syncthreads();

        // ---- tail: each thread reduces its (rb, rh) ----
        float r = (part[(0 + rb)*256 + rh] + part[(2 + rb)*256 + rh]) +
                  (part[(4 + rb)*256 + rh] + part[(6 + rb)*256 + rh]);
        const float* xsc = xs + cur*8 + rb*4;
        float xp = bi + wx.x*xsc[0] + wx.y*xsc[1] + wx.z*xsc[2] + wx.w*xsc[3];
        float hn = tanhf(xp + r);
        pool += hn;
        hbuf[nxt*512 + rb*256 + rh] = hn;
        __syncthreads();
        cur = nxt;
    }

    // ---- output head: out[b] = mean_t(h)[b] . W_h2o + b_h2o ----
    const float wo = W_h2o[rh];
    const float bo = b_h2o[0];
    float v = pool * wo;
    #pragma unroll
    for (int o = 16; o > 0; o >>= 1)
        v += __shfl_down_sync(0xffffffffu, v, o);
    if (l == 0) part[w] = v;        // warps 0-7: batch 0, warps 8-15: batch 1
    __syncthreads();
    if (t == 0) {
        float s = 0.0f;
        #pragma unroll
        for (int i = 0; i < 8; i++) s += part[i];
        out[b0] = s * (1.0f / 1024.0f) + bo;
    } else if (t == 1) {
        float s = 0.0f;
        #pragma unroll
        for (int i = 0; i < 8; i++) s += part[8 + i];
        out[b0 + 1] = s * (1.0f / 1024.0f) + bo;
    }
}

extern "C" void kernel_launch(void* const* d_in, const int* in_sizes, int n_in,
                              void* d_out, int out_size) {
    const float* x     = (const float*)d_in[0];
    const float* W_i2h = (const float*)d_in[1];
    const float* b_i2h = (const float*)d_in[2];
    const float* W_h2o = (const float*)d_in[3];
    const float* b_h2o = (const float*)d_in[4];
    const float* ih    = (const float*)d_in[5];
    float* outp = (float*)d_out;

    cudaFuncSetAttribute(rnn_kernel, cudaFuncAttributeMaxDynamicSharedMemorySize, SM_TOTAL);
    rnn_kernel<<<128, 512, SM_TOTAL>>>(x, W_i2h, b_i2h, W_h2o, b_h2o, ih, outp);
}

// round 8
// speedup vs baseline: 1.0747x; 1.0747x over previous
#include <cuda_runtime.h>

// RNN forward, fused persistent kernel. B=256, T=1024, IN=4, H=256, OUT=1.
// R7 (resubmit after 2nd infra failure): 128 CTAs x 512 threads (16 warps, 4/SMSP).
// CTA = 2 batches. Split: kg = w&3 (64 k each), hg = w>>2 (64 h each),
// 2 h-rows/thread. Wh: 40 u64-pairs/thread in regs (80 regs, fits <128),
// 12 ulonglong2/step streamed from smem. Tail: 1 (batch,h) per thread.

typedef unsigned long long u64;

#define T_LEN   1024

__device__ __forceinline__ u64 ffma2(u64 a, u64 b, u64 c) {
    u64 d;
    asm("fma.rn.f32x2 %0, %1, %2, %3;" : "=l"(d) : "l"(a), "l"(b), "l"(c));
    return d;
}
__device__ __forceinline__ float lo32(u64 v) { return __uint_as_float((unsigned)(v & 0xffffffffu)); }
__device__ __forceinline__ float hi32(u64 v) { return __uint_as_float((unsigned)(v >> 32)); }

// shared memory byte offsets
#define SM_WHS   0                  // ulonglong2 WHS[16][12][32]  = 98304 B
#define SM_PART  98304              // float part[8][256]          = 8192 B
#define SM_HBUF  106496             // float hbuf[2][2][256]       = 4096 B
#define SM_XS    110592             // float xs[2][2][4]           = 64 B
#define SM_TOTAL 110656

__global__ void __launch_bounds__(512, 1)
rnn_kernel(const float* __restrict__ x,        // [256][1024][4]
           const float* __restrict__ W_i2h,    // [256][260]  (cols 0..3 = Wx, 4..259 = Wh)
           const float* __restrict__ b_i2h,    // [256]
           const float* __restrict__ W_h2o,    // [256]
           const float* __restrict__ b_h2o,    // [1]
           const float* __restrict__ init_h,   // [256]
           float* __restrict__ out)            // [256]
{
    extern __shared__ unsigned char sm[];
    ulonglong2* WHS = (ulonglong2*)(sm + SM_WHS);
    float* part = (float*)(sm + SM_PART);       // part[kg*2+b][h]
    float* hbuf = (float*)(sm + SM_HBUF);       // hbuf[buf][b][256]
    float* xs   = (float*)(sm + SM_XS);         // xs[buf][b][4]

    const int t  = threadIdx.x;                 // 0..511
    const int w  = t >> 5;                      // 0..15
    const int l  = t & 31;
    const int kg = w & 3;                       // k in [64*kg, 64*kg+64)
    const int hg = w >> 2;                      // h in [64*hg, 64*hg+64)
    const int kbase = kg * 64;

    const int b0 = blockIdx.x * 2;
    const int rA = hg * 64 + l;                 // this thread's 2 h-rows
    const int rB = rA + 32;

    // ---- Wh: rowA all 32 pairs + rowB pairs 0..7 in regs (40 pairs = 80 regs);
    //      rowB pairs 8..31 in smem (12 ulonglong2 per thread = 96KB/CTA) ----
    u64 wreg[40];
    {
        const ulonglong2* rpA = (const ulonglong2*)(W_i2h + (size_t)rA * 260 + 4 + kbase);
        #pragma unroll
        for (int jj = 0; jj < 16; jj++) {
            ulonglong2 v = rpA[jj];
            wreg[2*jj]     = v.x;
            wreg[2*jj + 1] = v.y;
        }
        const ulonglong2* rpB = (const ulonglong2*)(W_i2h + (size_t)rB * 260 + 4 + kbase);
        #pragma unroll
        for (int jj = 0; jj < 4; jj++) {
            ulonglong2 v = rpB[jj];
            wreg[32 + 2*jj]     = v.x;
            wreg[32 + 2*jj + 1] = v.y;
        }
        #pragma unroll
        for (int jj = 4; jj < 16; jj++)
            WHS[(w*12 + (jj - 4))*32 + l] = rpB[jj];
    }

    // reducer role: one (batch, h) per thread
    const int rb = t >> 8;                      // 0 or 1
    const int rh = t & 255;                     // h index
    const float4 wx = *(const float4*)(W_i2h + (size_t)rh * 260);   // Wx[rh][0..3]
    const float bi = b_i2h[rh];

    // init hidden state (buffer 0) and x for step 0
    if (t < 256) {
        float hv = init_h[t];
        hbuf[0*512 + 0*256 + t] = hv;
        hbuf[0*512 + 1*256 + t] = hv;
    }
    if (t < 2) {
        float4 xv = *(const float4*)(x + ((size_t)(b0 + t) * T_LEN + 0) * 4);
        *(float4*)(xs + t*4) = xv;
    }
    __syncthreads();

    float pool = 0.0f;
    int cur = 0;

    for (int step = 0; step < T_LEN; step++) {
        const int nxt = cur ^ 1;

        // ---- FMA phase: partial dot products over this warp's 64-k slice ----
        const ulonglong2* hp0 = (const ulonglong2*)(hbuf + cur*512 + 0*256 + kbase);
        const ulonglong2* hp1 = (const ulonglong2*)(hbuf + cur*512 + 1*256 + kbase);

        u64 aA0 = 0ULL, aA1 = 0ULL, aB0 = 0ULL, aB1 = 0ULL;

        #pragma unroll
        for (int jj = 0; jj < 16; jj++) {
            ulonglong2 h0v = hp0[jj];
            ulonglong2 h1v = hp1[jj];
            u64 wa = wreg[2*jj];
            u64 wb = wreg[2*jj + 1];
            aA0 = ffma2(wa, h0v.x, aA0);
            aA0 = ffma2(wb, h0v.y, aA0);
            aA1 = ffma2(wa, h1v.x, aA1);
            aA1 = ffma2(wb, h1v.y, aA1);
            u64 wa2, wb2;
            if (jj < 4) { wa2 = wreg[32 + 2*jj]; wb2 = wreg[32 + 2*jj + 1]; }
            else { ulonglong2 v = WHS[(w*12 + (jj - 4))*32 + l]; wa2 = v.x; wb2 = v.y; }
            aB0 = ffma2(wa2, h0v.x, aB0);
            aB0 = ffma2(wb2, h0v.y, aB0);
            aB1 = ffma2(wa2, h1v.x, aB1);
            aB1 = ffma2(wb2, h1v.y, aB1);
        }

        // partial sums: part[kg*2+b][h]
        part[(kg*2 + 0)*256 + rA] = lo32(aA0) + hi32(aA0);
        part[(kg*2 + 1)*256 + rA] = lo32(aA1) + hi32(aA1);
        part[(kg*2 + 0)*256 + rB] = lo32(aB0) + hi32(aB0);
        part[(kg*2 + 1)*256 + rB] = lo32(aB1) + hi32(aB1);

        // stage x for next step
        if (t < 2) {
            int tn = (step < T_LEN - 1) ? (step + 1) : step;
            float4 xv = *(const float4*)(x + ((size_t)(b0 + t) * T_LEN + tn) * 4);
            *(float4*)(xs + nxt*8 + t*4) = xv;
        }
        __syncthreads();

        // ---- tail: each thread reduces its (rb, rh) ----
        float r = (part[(0 + rb)*256 + rh] + part[(2 + rb)*256 + rh]) +
                  (part[(4 + rb)*256 + rh] + part[(6 + rb)*256 + rh]);
        const float* xsc = xs + cur*8 + rb*4;
        float xp = bi + wx.x*xsc[0] + wx.y*xsc[1] + wx.z*xsc[2] + wx.w*xsc[3];
        float hn = tanhf(xp + r);
        pool += hn;
        hbuf[nxt*512 + rb*256 + rh] = hn;
        __syncthreads();
        cur = nxt;
    }

    // ---- output head: out[b] = mean_t(h)[b] . W_h2o + b_h2o ----
    const float wo = W_h2o[rh];
    const float bo = b_h2o[0];
    float v = pool * wo;
    #pragma unroll
    for (int o = 16; o > 0; o >>= 1)
        v += __shfl_down_sync(0xffffffffu, v, o);
    if (l == 0) part[w] = v;        // warps 0-7: batch 0, warps 8-15: batch 1
    __syncthreads();
    if (t == 0) {
        float s = 0.0f;
        #pragma unroll
        for (int i = 0; i < 8; i++) s += part[i];
        out[b0] = s * (1.0f / 1024.0f) + bo;
    } else if (t == 1) {
        float s = 0.0f;
        #pragma unroll
        for (int i = 0; i < 8; i++) s += part[8 + i];
        out[b0 + 1] = s * (1.0f / 1024.0f) + bo;
    }
}

extern "C" void kernel_launch(void* const* d_in, const int* in_sizes, int n_in,
                              void* d_out, int out_size) {
    const float* x     = (const float*)d_in[0];
    const float* W_i2h = (const float*)d_in[1];
    const float* b_i2h = (const float*)d_in[2];
    const float* W_h2o = (const float*)d_in[3];
    const float* b_h2o = (const float*)d_in[4];
    const float* ih    = (const float*)d_in[5];
    float* outp = (float*)d_out;

    cudaFuncSetAttribute(rnn_kernel, cudaFuncAttributeMaxDynamicSharedMemorySize, SM_TOTAL);
    rnn_kernel<<<128, 512, SM_TOTAL>>>(x, W_i2h, b_i2h, W_h2o, b_h2o, ih, outp);
}

// round 9
// speedup vs baseline: 1.2687x; 1.1805x over previous
#include <cuda_runtime.h>

// RNN forward, fused persistent kernel. B=256, T=1024, IN=4, H=256, OUT=1.
// 128 CTAs x 256 threads; CTA = 2 batches for all 1024 steps.
// R9 = R1 champion skeleton with ONE change: weight split 76 reg-pairs (was 88)
// + 26 ulonglong2/step streamed (was 20), freeing ~40 regs of scheduling slack
// so ptxas can hoist/pipeline the streamed weight LDS inside the FMA phase.

typedef unsigned long long u64;

#define T_LEN   1024
#define KG_LEN  64

__device__ __forceinline__ u64 ffma2(u64 a, u64 b, u64 c) {
    u64 d;
    asm("fma.rn.f32x2 %0, %1, %2, %3;" : "=l"(d) : "l"(a), "l"(b), "l"(c));
    return d;
}
__device__ __forceinline__ float lo32(u64 v) { return __uint_as_float((unsigned)(v & 0xffffffffu)); }
__device__ __forceinline__ float hi32(u64 v) { return __uint_as_float((unsigned)(v >> 32)); }

// shared memory byte offsets
#define SM_WHS   0                  // ulonglong2 WHS[8][26][32]   = 106496 B
#define SM_HBUF  106496             // float hbuf[2][2][256]       = 4096 B
#define SM_PART  110592             // float part[8][256]          = 8192 B
#define SM_XS    118784             // float xs[2][8]              = 64 B
#define SM_TOTAL 118848

__global__ void __launch_bounds__(256, 1)
rnn_kernel(const float* __restrict__ x,        // [256][1024][4]
           const float* __restrict__ W_i2h,    // [256][260]  (cols 0..3 = Wx, 4..259 = Wh)
           const float* __restrict__ b_i2h,    // [256]
           const float* __restrict__ W_h2o,    // [256]
           const float* __restrict__ b_h2o,    // [1]
           const float* __restrict__ init_h,   // [256]
           float* __restrict__ out)            // [256]
{
    extern __shared__ unsigned char sm[];
    ulonglong2* WHS = (ulonglong2*)(sm + SM_WHS);
    float* hbuf = (float*)(sm + SM_HBUF);
    float* part = (float*)(sm + SM_PART);
    float* xs   = (float*)(sm + SM_XS);

    const int t  = threadIdx.x;
    const int w  = t >> 5;
    const int l  = t & 31;
    const int kg = w & 3;             // k-group: k in [64*kg, 64*kg+64)
    const int hg = w >> 2;            // h-group: h in [128*hg, 128*hg+128)
    const int kbase = kg * KG_LEN;

    const int b0 = blockIdx.x * 2;
    const int h0r = hg * 128 + l;     // + i*32, i=0..3: this thread's 4 h-rows

    // ---- Wh: rows 0,1 fully + first 12 pairs of row 2 in registers (76 pairs);
    //      rest of row 2 (10 ull2) + all of row 3 (16 ull2) in smem: 26 ull2/thread ----
    u64 wreg[76];
    {
        #pragma unroll
        for (int i = 0; i < 2; i++) {
            const ulonglong2* rp = (const ulonglong2*)(W_i2h + (size_t)(h0r + i*32) * 260 + 4 + kbase);
            #pragma unroll
            for (int jj = 0; jj < 16; jj++) {
                ulonglong2 v = rp[jj];
                wreg[i*32 + 2*jj]     = v.x;
                wreg[i*32 + 2*jj + 1] = v.y;
            }
        }
        const ulonglong2* rp2 = (const ulonglong2*)(W_i2h + (size_t)(h0r + 2*32) * 260 + 4 + kbase);
        #pragma unroll
        for (int jj = 0; jj < 6; jj++) {
            ulonglong2 v = rp2[jj];
            wreg[64 + 2*jj]     = v.x;
            wreg[64 + 2*jj + 1] = v.y;
        }
        #pragma unroll
        for (int jj = 6; jj < 16; jj++)
            WHS[(w*26 + (jj - 6))*32 + l] = rp2[jj];
        const ulonglong2* rp3 = (const ulonglong2*)(W_i2h + (size_t)(h0r + 3*32) * 260 + 4 + kbase);
        #pragma unroll
        for (int jj = 0; jj < 16; jj++)
            WHS[(w*26 + 10 + jj)*32 + l] = rp3[jj];
    }

    // reducer-role parameters for h = t
    const float4 wx = *(const float4*)(W_i2h + (size_t)t * 260);   // Wx[t][0..3]
    const float bi = b_i2h[t];

    // init hidden state (buffer 0) and x for step 0
    {
        float hv = init_h[t];
        hbuf[0*512 + 0*256 + t] = hv;
        hbuf[0*512 + 1*256 + t] = hv;
        if (t < 2) {
            float4 xv = *(const float4*)(x + ((size_t)(b0 + t) * T_LEN + 0) * 4);
            *(float4*)(xs + t*4) = xv;
        }
    }
    __syncthreads();

    float pool0 = 0.0f, pool1 = 0.0f;
    int cur = 0;

    for (int step = 0; step < T_LEN; step++) {
        const int nxt = cur ^ 1;

        // prefetch x for next step (threads 0,1)
        float4 xv;
        if (t < 2) {
            int tn = (step < T_LEN - 1) ? (step + 1) : step;
            xv = *(const float4*)(x + ((size_t)(b0 + t) * T_LEN + tn) * 4);
        }

        // xproj for h = t (this thread's reducer role)
        const float* xsc = xs + cur*8;
        float xp0 = bi + wx.x*xsc[0] + wx.y*xsc[1] + wx.z*xsc[2] + wx.w*xsc[3];
        float xp1 = bi + wx.x*xsc[4] + wx.y*xsc[5] + wx.z*xsc[6] + wx.w*xsc[7];

        // ---- FMA phase: partial dot products over this warp's k range ----
        const ulonglong2* hp0 = (const ulonglong2*)(hbuf + cur*512 + 0*256 + kbase);
        const ulonglong2* hp1 = (const ulonglong2*)(hbuf + cur*512 + 1*256 + kbase);

        u64 acc[4][2];
        #pragma unroll
        for (int i = 0; i < 4; i++) { acc[i][0] = 0ULL; acc[i][1] = 0ULL; }

        #pragma unroll
        for (int jj = 0; jj < 16; jj++) {
            ulonglong2 h0v = hp0[jj];
            ulonglong2 h1v = hp1[jj];
            #pragma unroll
            for (int i = 0; i < 2; i++) {
                u64 wa = wreg[i*32 + 2*jj];
                u64 wb = wreg[i*32 + 2*jj + 1];
                acc[i][0] = ffma2(wa, h0v.x, acc[i][0]);
                acc[i][0] = ffma2(wb, h0v.y, acc[i][0]);
                acc[i][1] = ffma2(wa, h1v.x, acc[i][1]);
                acc[i][1] = ffma2(wb, h1v.y, acc[i][1]);
            }
            u64 wa2, wb2;
            if (jj < 6) { wa2 = wreg[64 + 2*jj]; wb2 = wreg[64 + 2*jj + 1]; }
            else { ulonglong2 v = WHS[(w*26 + (jj - 6))*32 + l]; wa2 = v.x; wb2 = v.y; }
            acc[2][0] = ffma2(wa2, h0v.x, acc[2][0]);
            acc[2][0] = ffma2(wb2, h0v.y, acc[2][0]);
            acc[2][1] = ffma2(wa2, h1v.x, acc[2][1]);
            acc[2][1] = ffma2(wb2, h1v.y, acc[2][1]);
            ulonglong2 v3 = WHS[(w*26 + 10 + jj)*32 + l];
            acc[3][0] = ffma2(v3.x, h0v.x, acc[3][0]);
            acc[3][0] = ffma2(v3.y, h0v.y, acc[3][0]);
            acc[3][1] = ffma2(v3.x, h1v.x, acc[3][1]);
            acc[3][1] = ffma2(v3.y, h1v.y, acc[3][1]);
        }

        // write partial sums: part[kg*2+b][h]
        #pragma unroll
        for (int i = 0; i < 4; i++) {
            int hh = h0r + i*32;
            part[(kg*2 + 0)*256 + hh] = lo32(acc[i][0]) + hi32(acc[i][0]);
            part[(kg*2 + 1)*256 + hh] = lo32(acc[i][1]) + hi32(acc[i][1]);
        }
        __syncthreads();

        // ---- reduce across the 4 k-groups for h = t, tanh, pool, store state ----
        float pre0 = xp0 + ((part[0*256 + t] + part[2*256 + t]) +
                            (part[4*256 + t] + part[6*256 + t]));
        float pre1 = xp1 + ((part[1*256 + t] + part[3*256 + t]) +
                            (part[5*256 + t] + part[7*256 + t]));
        float hn0 = tanhf(pre0);
        float hn1 = tanhf(pre1);
        pool0 += hn0;
        pool1 += hn1;
        hbuf[nxt*512 + 0*256 + t] = hn0;
        hbuf[nxt*512 + 1*256 + t] = hn1;
        if (t < 2) *(float4*)(xs + nxt*8 + t*4) = xv;
        __syncthreads();
        cur = nxt;
    }

    // ---- output head: out[b] = mean_t(h)[b] . W_h2o + b_h2o ----
    const float wo = W_h2o[t];
    const float bo = b_h2o[0];
    float v0 = pool0 * (1.0f / 1024.0f) * wo;
    float v1 = pool1 * (1.0f / 1024.0f) * wo;
    #pragma unroll
    for (int o = 16; o > 0; o >>= 1) {
        v0 += __shfl_down_sync(0xffffffffu, v0, o);
        v1 += __shfl_down_sync(0xffffffffu, v1, o);
    }
    if (l == 0) { part[w] = v0; part[8 + w] = v1; }
    __syncthreads();
    if (t == 0) {
        float s = 0.0f;
        #pragma unroll
        for (int i = 0; i < 8; i++) s += part[i];
        out[b0] = s + bo;
    } else if (t == 1) {
        float s = 0.0f;
        #pragma unroll
        for (int i = 0; i < 8; i++) s += part[8 + i];
        out[b0 + 1] = s + bo;
    }
}

extern "C" void kernel_launch(void* const* d_in, const int* in_sizes, int n_in,
                              void* d_out, int out_size) {
    const float* x     = (const float*)d_in[0];
    const float* W_i2h = (const float*)d_in[1];
    const float* b_i2h = (const float*)d_in[2];
    const float* W_h2o = (const float*)d_in[3];
    const float* b_h2o = (const float*)d_in[4];
    const float* ih    = (const float*)d_in[5];
    float* outp = (float*)d_out;

    cudaFuncSetAttribute(rnn_kernel, cudaFuncAttributeMaxDynamicSharedMemorySize, SM_TOTAL);
    rnn_kernel<<<128, 256, SM_TOTAL>>>(x, W_i2h, b_i2h, W_h2o, b_h2o, ih, outp);
}

// round 10
// speedup vs baseline: 1.3007x; 1.0253x over previous
#include <cuda_runtime.h>

// RNN forward, fused persistent kernel. B=256, T=1024, IN=4, H=256, OUT=1.
// 128 CTAs x 256 threads; CTA = 2 batches for all 1024 steps.
// R10 = R1 champion with ONE change: warp remap kg=w>>1, hg=w&1 so each
// warp-PAIR p={2p,2p+1} produces AND consumes h-slice [64p,64p+64); the h
// hand-off barrier becomes a per-pair bar.sync(1+p,64) instead of a full
// __syncthreads. Traffic, FMA loop, weight split (88 reg-pairs + 20 ull2
// streamed), tanhf, x staging: all identical to R1.

typedef unsigned long long u64;

#define T_LEN   1024
#define KG_LEN  64

__device__ __forceinline__ u64 ffma2(u64 a, u64 b, u64 c) {
    u64 d;
    asm("fma.rn.f32x2 %0, %1, %2, %3;" : "=l"(d) : "l"(a), "l"(b), "l"(c));
    return d;
}
__device__ __forceinline__ float lo32(u64 v) { return __uint_as_float((unsigned)(v & 0xffffffffu)); }
__device__ __forceinline__ float hi32(u64 v) { return __uint_as_float((unsigned)(v >> 32)); }

// shared memory byte offsets
#define SM_WHS   0                  // ulonglong2 WHS[8][20][32]   = 81920 B
#define SM_HBUF  81920              // float hbuf[2][2][256]       = 4096 B
#define SM_PART  86016              // float part[8][256]          = 8192 B
#define SM_XS    94208              // float xs[2][8]              = 64 B
#define SM_TOTAL 94272

__global__ void __launch_bounds__(256, 1)
rnn_kernel(const float* __restrict__ x,        // [256][1024][4]
           const float* __restrict__ W_i2h,    // [256][260]  (cols 0..3 = Wx, 4..259 = Wh)
           const float* __restrict__ b_i2h,    // [256]
           const float* __restrict__ W_h2o,    // [256]
           const float* __restrict__ b_h2o,    // [1]
           const float* __restrict__ init_h,   // [256]
           float* __restrict__ out)            // [256]
{
    extern __shared__ unsigned char sm[];
    ulonglong2* WHS = (ulonglong2*)(sm + SM_WHS);
    float* hbuf = (float*)(sm + SM_HBUF);
    float* part = (float*)(sm + SM_PART);
    float* xs   = (float*)(sm + SM_XS);

    const int t  = threadIdx.x;
    const int w  = t >> 5;
    const int l  = t & 31;
    const int kg = w >> 1;            // k-group: k in [64*kg, 64*kg+64)  (pair id)
    const int hg = w & 1;             // h-group: h in [128*hg, 128*hg+128)
    const int kbase = kg * KG_LEN;
    const int pairbar = 1 + kg;       // named barrier per warp-pair {2kg, 2kg+1}

    const int b0 = blockIdx.x * 2;
    const int h0r = hg * 128 + l;     // + i*32, i=0..3: this thread's 4 h-rows

    // ---- Wh: rows 0,1 + first 24 pairs of row 2 in registers (88 pairs = 176 regs);
    //      rest of row 2 + all of row 3 in smem (20 ulonglong2 per thread = 80KB/CTA) ----
    u64 wreg[88];
    {
        #pragma unroll
        for (int i = 0; i < 2; i++) {
            const ulonglong2* rp = (const ulonglong2*)(W_i2h + (size_t)(h0r + i*32) * 260 + 4 + kbase);
            #pragma unroll
            for (int jj = 0; jj < 16; jj++) {
                ulonglong2 v = rp[jj];
                wreg[i*32 + 2*jj]     = v.x;
                wreg[i*32 + 2*jj + 1] = v.y;
            }
        }
        const ulonglong2* rp2 = (const ulonglong2*)(W_i2h + (size_t)(h0r + 2*32) * 260 + 4 + kbase);
        #pragma unroll
        for (int jj = 0; jj < 12; jj++) {
            ulonglong2 v = rp2[jj];
            wreg[64 + 2*jj]     = v.x;
            wreg[64 + 2*jj + 1] = v.y;
        }
        #pragma unroll
        for (int jj = 12; jj < 16; jj++)
            WHS[(w*20 + (jj - 12))*32 + l] = rp2[jj];
        const ulonglong2* rp3 = (const ulonglong2*)(W_i2h + (size_t)(h0r + 3*32) * 260 + 4 + kbase);
        #pragma unroll
        for (int jj = 0; jj < 16; jj++)
            WHS[(w*20 + 4 + jj)*32 + l] = rp3[jj];
    }

    // reducer-role parameters for h = t (thread t reduces h=t; t is inside
    // warp-pair kg's h-slice [64*kg, 64*kg+64) by construction)
    const float4 wx = *(const float4*)(W_i2h + (size_t)t * 260);   // Wx[t][0..3]
    const float bi = b_i2h[t];

    // init hidden state (buffer 0) and x for step 0
    {
        float hv = init_h[t];
        hbuf[0*512 + 0*256 + t] = hv;
        hbuf[0*512 + 1*256 + t] = hv;
        if (t < 2) {
            float4 xv = *(const float4*)(x + ((size_t)(b0 + t) * T_LEN + 0) * 4);
            *(float4*)(xs + t*4) = xv;
        }
    }
    __syncthreads();

    float pool0 = 0.0f, pool1 = 0.0f;
    int cur = 0;

    for (int step = 0; step < T_LEN; step++) {
        const int nxt = cur ^ 1;

        // prefetch x for next step (threads 0,1)
        float4 xv;
        if (t < 2) {
            int tn = (step < T_LEN - 1) ? (step + 1) : step;
            xv = *(const float4*)(x + ((size_t)(b0 + t) * T_LEN + tn) * 4);
        }

        // xproj for h = t (this thread's reducer role)
        const float* xsc = xs + cur*8;
        float xp0 = bi + wx.x*xsc[0] + wx.y*xsc[1] + wx.z*xsc[2] + wx.w*xsc[3];
        float xp1 = bi + wx.x*xsc[4] + wx.y*xsc[5] + wx.z*xsc[6] + wx.w*xsc[7];

        // ---- FMA phase: partial dot products over this warp's k range ----
        const ulonglong2* hp0 = (const ulonglong2*)(hbuf + cur*512 + 0*256 + kbase);
        const ulonglong2* hp1 = (const ulonglong2*)(hbuf + cur*512 + 1*256 + kbase);

        u64 acc[4][2];
        #pragma unroll
        for (int i = 0; i < 4; i++) { acc[i][0] = 0ULL; acc[i][1] = 0ULL; }

        #pragma unroll
        for (int jj = 0; jj < 16; jj++) {
            ulonglong2 h0v = hp0[jj];
            ulonglong2 h1v = hp1[jj];
            #pragma unroll
            for (int i = 0; i < 2; i++) {
                u64 wa = wreg[i*32 + 2*jj];
                u64 wb = wreg[i*32 + 2*jj + 1];
                acc[i][0] = ffma2(wa, h0v.x, acc[i][0]);
                acc[i][0] = ffma2(wb, h0v.y, acc[i][0]);
                acc[i][1] = ffma2(wa, h1v.x, acc[i][1]);
                acc[i][1] = ffma2(wb, h1v.y, acc[i][1]);
            }
            u64 wa2, wb2;
            if (jj < 12) { wa2 = wreg[64 + 2*jj]; wb2 = wreg[64 + 2*jj + 1]; }
            else { ulonglong2 v = WHS[(w*20 + (jj - 12))*32 + l]; wa2 = v.x; wb2 = v.y; }
            acc[2][0] = ffma2(wa2, h0v.x, acc[2][0]);
            acc[2][0] = ffma2(wb2, h0v.y, acc[2][0]);
            acc[2][1] = ffma2(wa2, h1v.x, acc[2][1]);
            acc[2][1] = ffma2(wb2, h1v.y, acc[2][1]);
            ulonglong2 v3 = WHS[(w*20 + 4 + jj)*32 + l];
            acc[3][0] = ffma2(v3.x, h0v.x, acc[3][0]);
            acc[3][0] = ffma2(v3.y, h0v.y, acc[3][0]);
            acc[3][1] = ffma2(v3.x, h1v.x, acc[3][1]);
            acc[3][1] = ffma2(v3.y, h1v.y, acc[3][1]);
        }

        // write partial sums: part[kg*2+b][h]
        #pragma unroll
        for (int i = 0; i < 4; i++) {
            int hh = h0r + i*32;
            part[(kg*2 + 0)*256 + hh] = lo32(acc[i][0]) + hi32(acc[i][0]);
            part[(kg*2 + 1)*256 + hh] = lo32(acc[i][1]) + hi32(acc[i][1]);
        }

        // stage x for next step (xs double-buffered; consumed after next B1)
        if (t < 2) *(float4*)(xs + nxt*8 + t*4) = xv;

        // B1: full barrier — partials cross warp-pairs
        __syncthreads();

        // ---- reduce across the 4 k-groups for h = t, tanh, pool, store state ----
        float r0 = (part[0*256 + t] + part[2*256 + t]) +
                   (part[4*256 + t] + part[6*256 + t]);
        float r1 = (part[1*256 + t] + part[3*256 + t]) +
                   (part[5*256 + t] + part[7*256 + t]);
        float hn0 = tanhf(xp0 + r0);
        float hn1 = tanhf(xp1 + r1);
        pool0 += hn0;
        pool1 += hn1;
        hbuf[nxt*512 + 0*256 + t] = hn0;
        hbuf[nxt*512 + 1*256 + t] = hn1;

        // B2: per-pair barrier — h-slice [64*kg, 64*kg+64) is produced and
        // consumed entirely within warp-pair {2kg, 2kg+1}
        asm volatile("bar.sync %0, 64;" :: "r"(pairbar) : "memory");
        cur = nxt;
    }

    // ---- output head: out[b] = mean_t(h)[b] . W_h2o + b_h2o ----
    __syncthreads();
    const float wo = W_h2o[t];
    const float bo = b_h2o[0];
    float v0 = pool0 * (1.0f / 1024.0f) * wo;
    float v1 = pool1 * (1.0f / 1024.0f) * wo;
    #pragma unroll
    for (int o = 16; o > 0; o >>= 1) {
        v0 += __shfl_down_sync(0xffffffffu, v0, o);
        v1 += __shfl_down_sync(0xffffffffu, v1, o);
    }
    if (l == 0) { part[w] = v0; part[8 + w] = v1; }
    __syncthreads();
    if (t == 0) {
        float s = 0.0f;
        #pragma unroll
        for (int i = 0; i < 8; i++) s += part[i];
        out[b0] = s + bo;
    } else if (t == 1) {
        float s = 0.0f;
        #pragma unroll
        for (int i = 0; i < 8; i++) s += part[8 + i];
        out[b0 + 1] = s + bo;
    }
}

extern "C" void kernel_launch(void* const* d_in, const int* in_sizes, int n_in,
                              void* d_out, int out_size) {
    const float* x     = (const float*)d_in[0];
    const float* W_i2h = (const float*)d_in[1];
    const float* b_i2h = (const float*)d_in[2];
    const float* W_h2o = (const float*)d_in[3];
    const float* b_h2o = (const float*)d_in[4];
    const float* ih    = (const float*)d_in[5];
    float* outp = (float*)d_out;

    cudaFuncSetAttribute(rnn_kernel, cudaFuncAttributeMaxDynamicSharedMemorySize, SM_TOTAL);
    rnn_kernel<<<128, 256, SM_TOTAL>>>(x, W_i2h, b_i2h, W_h2o, b_h2o, ih, outp);
}

// round 11
// speedup vs baseline: 1.3441x; 1.0334x over previous
#include <cuda_runtime.h>

// RNN forward, fused persistent kernel. B=256, T=1024, IN=4, H=256, OUT=1.
// 128 CTAs x 256 threads; CTA = 2 batches for all 1024 steps.
// R11 = R1 champion + three tail-shortening deltas:
//  (1) accumulator rows permuted per warp (row_i = h0r + 32*((i+kg)&3)) so
//      acc[0] is ALWAYS the partial for h = threadIdx; it stays in registers
//      (skip its STS + LDS entirely).
//  (2) part relayout float2[4][256]: 3 STS.64 + 3 LDS.64 per thread per step.
//  (3) branchless fast_tanh (EX2+RCP) instead of tanhf.
// Weight split (88 reg-pairs + 20 ull2 streamed), barriers, x staging: R1 exact.

typedef unsigned long long u64;

#define T_LEN   1024
#define KG_LEN  64

__device__ __forceinline__ u64 ffma2(u64 a, u64 b, u64 c) {
    u64 d;
    asm("fma.rn.f32x2 %0, %1, %2, %3;" : "=l"(d) : "l"(a), "l"(b), "l"(c));
    return d;
}
__device__ __forceinline__ float lo32(u64 v) { return __uint_as_float((unsigned)(v & 0xffffffffu)); }
__device__ __forceinline__ float hi32(u64 v) { return __uint_as_float((unsigned)(v >> 32)); }

__device__ __forceinline__ float fast_tanh(float x) {
    float a = fabsf(x);
    float e = __expf(2.0f * a);
    float r = 1.0f - __fdividef(2.0f, e + 1.0f);
    return copysignf(r, x);
}

// shared memory byte offsets
#define SM_WHS   0                  // ulonglong2 WHS[8][20][32]   = 81920 B
#define SM_HBUF  81920              // float hbuf[2][2][256]       = 4096 B
#define SM_PART  86016              // float2 part[4][256]         = 8192 B
#define SM_XS    94208              // float xs[2][8]              = 64 B
#define SM_TOTAL 94272

__global__ void __launch_bounds__(256, 1)
rnn_kernel(const float* __restrict__ x,        // [256][1024][4]
           const float* __restrict__ W_i2h,    // [256][260]  (cols 0..3 = Wx, 4..259 = Wh)
           const float* __restrict__ b_i2h,    // [256]
           const float* __restrict__ W_h2o,    // [256]
           const float* __restrict__ b_h2o,    // [1]
           const float* __restrict__ init_h,   // [256]
           float* __restrict__ out)            // [256]
{
    extern __shared__ unsigned char sm[];
    ulonglong2* WHS = (ulonglong2*)(sm + SM_WHS);
    float* hbuf = (float*)(sm + SM_HBUF);
    float2* part2 = (float2*)(sm + SM_PART);    // part2[kg*256 + h] = {b0, b1}
    float* part = (float*)(sm + SM_PART);       // alias for head scratch
    float* xs   = (float*)(sm + SM_XS);

    const int t  = threadIdx.x;
    const int w  = t >> 5;
    const int l  = t & 31;
    const int kg = w & 3;             // k-group: k in [64*kg, 64*kg+64)
    const int hg = w >> 2;            // h-group: h in [128*hg, 128*hg+128)
    const int kbase = kg * KG_LEN;

    const int b0 = blockIdx.x * 2;
    const int h0r = hg * 128 + l;

    // permuted row assignment: row_i = h0r + 32*((i + kg) & 3); row_0 == t
    const int row1 = h0r + 32 * ((kg + 1) & 3);
    const int row2 = h0r + 32 * ((kg + 2) & 3);
    const int row3 = h0r + 32 * ((kg + 3) & 3);

    // ---- Wh: row0 (== t) and row1 fully + first 24 pairs of row2 in registers
    //      (88 pairs = 176 regs); rest of row2 + all of row3 in smem
    //      (20 ulonglong2 per thread = 80KB/CTA) ----
    u64 wreg[88];
    {
        const ulonglong2* rp0 = (const ulonglong2*)(W_i2h + (size_t)t * 260 + 4 + kbase);
        #pragma unroll
        for (int jj = 0; jj < 16; jj++) {
            ulonglong2 v = rp0[jj];
            wreg[2*jj]     = v.x;
            wreg[2*jj + 1] = v.y;
        }
        const ulonglong2* rp1 = (const ulonglong2*)(W_i2h + (size_t)row1 * 260 + 4 + kbase);
        #pragma unroll
        for (int jj = 0; jj < 16; jj++) {
            ulonglong2 v = rp1[jj];
            wreg[32 + 2*jj]     = v.x;
            wreg[32 + 2*jj + 1] = v.y;
        }
        const ulonglong2* rp2 = (const ulonglong2*)(W_i2h + (size_t)row2 * 260 + 4 + kbase);
        #pragma unroll
        for (int jj = 0; jj < 12; jj++) {
            ulonglong2 v = rp2[jj];
            wreg[64 + 2*jj]     = v.x;
            wreg[64 + 2*jj + 1] = v.y;
        }
        #pragma unroll
        for (int jj = 12; jj < 16; jj++)
            WHS[(w*20 + (jj - 12))*32 + l] = rp2[jj];
        const ulonglong2* rp3 = (const ulonglong2*)(W_i2h + (size_t)row3 * 260 + 4 + kbase);
        #pragma unroll
        for (int jj = 0; jj < 16; jj++)
            WHS[(w*20 + 4 + jj)*32 + l] = rp3[jj];
    }

    // reducer-role parameters for h = t
    const float4 wx = *(const float4*)(W_i2h + (size_t)t * 260);   // Wx[t][0..3]
    const float bi = b_i2h[t];
    const float wo = W_h2o[t];
    const float bo = b_h2o[0];

    // init hidden state (buffer 0) and x for step 0
    {
        float hv = init_h[t];
        hbuf[0*512 + 0*256 + t] = hv;
        hbuf[0*512 + 1*256 + t] = hv;
        if (t < 2) {
            float4 xv = *(const float4*)(x + ((size_t)(b0 + t) * T_LEN + 0) * 4);
            *(float4*)(xs + t*4) = xv;
        }
    }
    __syncthreads();

    float pool0 = 0.0f, pool1 = 0.0f;
    int cur = 0;

    // tail load offsets for the 3 other k-groups (element index into part2)
    const int o1 = ((kg + 1) & 3) * 256 + t;
    const int o2 = ((kg + 2) & 3) * 256 + t;
    const int o3 = ((kg + 3) & 3) * 256 + t;

    for (int step = 0; step < T_LEN; step++) {
        const int nxt = cur ^ 1;

        // prefetch x for next step (threads 0,1)
        float4 xv;
        if (t < 2) {
            int tn = (step < T_LEN - 1) ? (step + 1) : step;
            xv = *(const float4*)(x + ((size_t)(b0 + t) * T_LEN + tn) * 4);
        }

        // xproj for h = t
        const float* xsc = xs + cur*8;
        float xp0 = bi + wx.x*xsc[0] + wx.y*xsc[1] + wx.z*xsc[2] + wx.w*xsc[3];
        float xp1 = bi + wx.x*xsc[4] + wx.y*xsc[5] + wx.z*xsc[6] + wx.w*xsc[7];

        // ---- FMA phase: partial dot products over this warp's k range ----
        const ulonglong2* hp0 = (const ulonglong2*)(hbuf + cur*512 + 0*256 + kbase);
        const ulonglong2* hp1 = (const ulonglong2*)(hbuf + cur*512 + 1*256 + kbase);

        u64 acc[4][2];
        #pragma unroll
        for (int i = 0; i < 4; i++) { acc[i][0] = 0ULL; acc[i][1] = 0ULL; }

        #pragma unroll
        for (int jj = 0; jj < 16; jj++) {
            ulonglong2 h0v = hp0[jj];
            ulonglong2 h1v = hp1[jj];
            #pragma unroll
            for (int i = 0; i < 2; i++) {
                u64 wa = wreg[i*32 + 2*jj];
                u64 wb = wreg[i*32 + 2*jj + 1];
                acc[i][0] = ffma2(wa, h0v.x, acc[i][0]);
                acc[i][0] = ffma2(wb, h0v.y, acc[i][0]);
                acc[i][1] = ffma2(wa, h1v.x, acc[i][1]);
                acc[i][1] = ffma2(wb, h1v.y, acc[i][1]);
            }
            u64 wa2, wb2;
            if (jj < 12) { wa2 = wreg[64 + 2*jj]; wb2 = wreg[64 + 2*jj + 1]; }
            else { ulonglong2 v = WHS[(w*20 + (jj - 12))*32 + l]; wa2 = v.x; wb2 = v.y; }
            acc[2][0] = ffma2(wa2, h0v.x, acc[2][0]);
            acc[2][0] = ffma2(wb2, h0v.y, acc[2][0]);
            acc[2][1] = ffma2(wa2, h1v.x, acc[2][1]);
            acc[2][1] = ffma2(wb2, h1v.y, acc[2][1]);
            ulonglong2 v3 = WHS[(w*20 + 4 + jj)*32 + l];
            acc[3][0] = ffma2(v3.x, h0v.x, acc[3][0]);
            acc[3][0] = ffma2(v3.y, h0v.y, acc[3][0]);
            acc[3][1] = ffma2(v3.x, h1v.x, acc[3][1]);
            acc[3][1] = ffma2(v3.y, h1v.y, acc[3][1]);
        }

        // own partial (row_0 == t): keep in registers, skip store+load
        float s00 = lo32(acc[0][0]) + hi32(acc[0][0]);
        float s01 = lo32(acc[0][1]) + hi32(acc[0][1]);

        // store the 3 foreign partials: part2[kg*256 + row] = {b0, b1}
        {
            float2* pp = part2 + kg * 256;
            pp[row1] = make_float2(lo32(acc[1][0]) + hi32(acc[1][0]),
                                   lo32(acc[1][1]) + hi32(acc[1][1]));
            pp[row2] = make_float2(lo32(acc[2][0]) + hi32(acc[2][0]),
                                   lo32(acc[2][1]) + hi32(acc[2][1]));
            pp[row3] = make_float2(lo32(acc[3][0]) + hi32(acc[3][0]),
                                   lo32(acc[3][1]) + hi32(acc[3][1]));
        }
        __syncthreads();

        // ---- tail: reduce 3 foreign partials + own, tanh, pool, store state ----
        float2 pa = part2[o1];
        float2 pb = part2[o2];
        float2 pc = part2[o3];
        float r0 = s00 + ((pa.x + pb.x) + pc.x);
        float r1 = s01 + ((pa.y + pb.y) + pc.y);
        float hn0 = fast_tanh(xp0 + r0);
        float hn1 = fast_tanh(xp1 + r1);
        pool0 += hn0;
        pool1 += hn1;
        hbuf[nxt*512 + 0*256 + t] = hn0;
        hbuf[nxt*512 + 1*256 + t] = hn1;
        if (t < 2) *(float4*)(xs + nxt*8 + t*4) = xv;
        __syncthreads();
        cur = nxt;
    }

    // ---- output head: out[b] = mean_t(h)[b] . W_h2o + b_h2o ----
    float v0 = pool0 * (1.0f / 1024.0f) * wo;
    float v1 = pool1 * (1.0f / 1024.0f) * wo;
    #pragma unroll
    for (int o = 16; o > 0; o >>= 1) {
        v0 += __shfl_down_sync(0xffffffffu, v0, o);
        v1 += __shfl_down_sync(0xffffffffu, v1, o);
    }
    if (l == 0) { part[w] = v0; part[8 + w] = v1; }
    __syncthreads();
    if (t == 0) {
        float s = 0.0f;
        #pragma unroll
        for (int i = 0; i < 8; i++) s += part[i];
        out[b0] = s + bo;
    } else if (t == 1) {
        float s = 0.0f;
        #pragma unroll
        for (int i = 0; i < 8; i++) s += part[8 + i];
        out[b0 + 1] = s + bo;
    }
}

extern "C" void kernel_launch(void* const* d_in, const int* in_sizes, int n_in,
                              void* d_out, int out_size) {
    const float* x     = (const float*)d_in[0];
    const float* W_i2h = (const float*)d_in[1];
    const float* b_i2h = (const float*)d_in[2];
    const float* W_h2o = (const float*)d_in[3];
    const float* b_h2o = (const float*)d_in[4];
    const float* ih    = (const float*)d_in[5];
    float* outp = (float*)d_out;

    cudaFuncSetAttribute(rnn_kernel, cudaFuncAttributeMaxDynamicSharedMemorySize, SM_TOTAL);
    rnn_kernel<<<128, 256, SM_TOTAL>>>(x, W_i2h, b_i2h, W_h2o, b_h2o, ih, outp);
}